// round 3
// baseline (speedup 1.0000x reference)
#include <cuda_runtime.h>

// DeepAR forward: 2-layer LSTM (H=64) over T=383 steps, 16384 independent
// sequences. Persistent kernel: 256 CTAs x 256 threads, each CTA owns 64
// sequences end-to-end (no grid sync needed). Weights live in shared memory
// (fp32, transposed for conflict-free LDS); h-state in shared (transposed
// [j][s] so sequence pairs are contiguous -> LDS.64); c-state in registers.
// Inner product uses Blackwell packed fma.rn.f32x2: 2 sequences per lane.

#define TPB 256
#define SEQ 64          // sequences per CTA
#define NCTA 256        // 256 * 64 = 16384 sequences
#define NSTEP 383
#define HP 66           // h-state pitch (padded, even for 8B alignment)

// shared layout (floats)
#define OFF_WT0 0               // [64][256]  W_hh0^T            16384
#define OFF_WT1 16384           // [128][256] [W_ih1;W_hh1]^T    32768
#define OFF_H0  49152           // [64][HP]                       4224
#define OFF_H1  53376           // [64][HP]                       4224
#define OFF_XS  57600           // [64][5]  prev + 4 covariates    320
#define OFF_HW  57920           // head_W (2x64)                   128
#define OFF_HB  58048           // head_b                            2
#define SM_FLOATS 58050
#define SM_BYTES (SM_FLOATS * 4)

typedef unsigned long long ull;

static __device__ __forceinline__ ull pk2(float a, float b) {
    ull r; asm("mov.b64 %0, {%1, %2};" : "=l"(r) : "f"(a), "f"(b)); return r;
}
static __device__ __forceinline__ void upk2(ull v, float& a, float& b) {
    asm("mov.b64 {%0, %1}, %2;" : "=f"(a), "=f"(b) : "l"(v));
}
static __device__ __forceinline__ ull fma2(ull a, ull b, ull c) {
    ull d; asm("fma.rn.f32x2 %0, %1, %2, %3;" : "=l"(d) : "l"(a), "l"(b), "l"(c)); return d;
}

static __device__ __forceinline__ float sigm_(float x) {
    return __fdividef(1.f, 1.f + __expf(-x));
}
static __device__ __forceinline__ float tanh_(float x) {
    // 1 - 2/(e^{2x}+1): exact at saturation (exp->0 or inf), ~1e-6 rel err.
    float e = __expf(2.f * x);
    return 1.f - __fdividef(2.f, e + 1.f);
}

// Accumulate acc[g][pair] += W^T[j][g*64+u] * h[j][pair] over 64 j-rows.
// W column-major-in-row layout: W[j*256 + row]; H: [j][HP] with base offset
// already including this thread's sequence-block start (sbase).
static __device__ __forceinline__ void mv64(ull (&acc)[4][8],
                                            const float* __restrict__ W,
                                            const float* __restrict__ H,
                                            int u) {
#pragma unroll 8
    for (int j = 0; j < 64; j++) {
        const float* wr = W + j * 256 + u;
        float w0 = wr[0], w1 = wr[64], w2 = wr[128], w3 = wr[192];
        ull W0 = pk2(w0, w0), W1 = pk2(w1, w1), W2 = pk2(w2, w2), W3 = pk2(w3, w3);
        const ull* hr = (const ull*)(H + j * HP);
#pragma unroll
        for (int p = 0; p < 8; p++) {
            ull h = hr[p];
            acc[0][p] = fma2(W0, h, acc[0][p]);
            acc[1][p] = fma2(W1, h, acc[1][p]);
            acc[2][p] = fma2(W2, h, acc[2][p]);
            acc[3][p] = fma2(W3, h, acc[3][p]);
        }
    }
}

extern "C" __global__ void __launch_bounds__(TPB, 1)
deepar_kernel(const float* __restrict__ hist,   // (32,336,512,5)
              const float* __restrict__ fut,    // (32, 48,512,5)
              const float* __restrict__ emb_W,  // (32,1)
              const float* __restrict__ emb_b,  // (32)
              const float* __restrict__ W_ih0,  // (256,36)
              const float* __restrict__ W_hh0,  // (256,64)
              const float* __restrict__ b_ih0,
              const float* __restrict__ b_hh0,
              const float* __restrict__ W_ih1,  // (256,64)
              const float* __restrict__ W_hh1,  // (256,64)
              const float* __restrict__ b_ih1,
              const float* __restrict__ b_hh1,
              const float* __restrict__ head_W, // (2,64)
              const float* __restrict__ head_b, // (2)
              float* __restrict__ out)          // (32,48,512,2)
{
    extern __shared__ float sm[];
    float* Wt0 = sm + OFF_WT0;
    float* Wt1 = sm + OFF_WT1;
    float* h0T = sm + OFF_H0;
    float* h1T = sm + OFF_H1;
    float* xs  = sm + OFF_XS;
    float* hw  = sm + OFF_HW;
    float* hb  = sm + OFF_HB;

    const int tid = threadIdx.x;
    const int u = tid & 63;         // hidden unit this thread owns
    const int sg = tid >> 6;        // sequence group 0..3 (16 seqs each)
    const int sbase = sg * 16;      // local seq base
    const int gbase = blockIdx.x * SEQ;

    // ---- load weights into shared (transposed: [j][row]) ----
    for (int e = tid; e < 256 * 64; e += TPB) {
        int row = e >> 6, j = e & 63;
        Wt0[j * 256 + row] = W_hh0[e];
        Wt1[j * 256 + row] = W_ih1[e];
        Wt1[(64 + j) * 256 + row] = W_hh1[e];
    }
    for (int e = tid; e < 64 * HP; e += TPB) { h0T[e] = 0.f; h1T[e] = 0.f; }
    if (tid < 128) hw[tid] = head_W[tid];
    if (tid < 2)   hb[tid] = head_b[tid];

    // ---- fold rank-1 embedding into per-gate scalar coefficients ----
    // pre0[row] = prev * v1[row] + cov . Wc[row] + v2[row]
    float v1r[4], v2r[4], wcr[4][4], b1r[4];
#pragma unroll
    for (int g = 0; g < 4; g++) {
        int r = g * 64 + u;
        const float* wr = W_ih0 + r * 36;
        float a = 0.f, bb = 0.f;
#pragma unroll
        for (int e = 0; e < 32; e++) {
            a  = fmaf(wr[e], emb_W[e], a);
            bb = fmaf(wr[e], emb_b[e], bb);
        }
        v1r[g] = a;
        v2r[g] = bb + b_ih0[r] + b_hh0[r];
#pragma unroll
        for (int k = 0; k < 4; k++) wcr[g][k] = wr[32 + k];
        b1r[g] = b_ih1[r] + b_hh1[r];
    }

    float c0v[16], c1v[16];
#pragma unroll
    for (int i = 0; i < 16; i++) { c0v[i] = 0.f; c1v[i] = 0.f; }

    __syncthreads();

    for (int t = 0; t < NSTEP; t++) {
        // ---- stage x_t (prev target + next-step covariates), 1 seq/thread ----
        if (tid < SEQ) {
            int gs = gbase + tid;
            int b = gs >> 9, n = gs & 511;
            const float* s1 = (t < 336)
                ? hist + (((size_t)b * 336 + t) * 512 + n) * 5
                : fut  + (((size_t)b * 48 + (t - 336)) * 512 + n) * 5;
            int tc = t + 1;
            const float* s2 = (tc < 336)
                ? hist + (((size_t)b * 336 + tc) * 512 + n) * 5
                : fut  + (((size_t)b * 48 + (tc - 336)) * 512 + n) * 5;
            float* xp = xs + tid * 5;
            xp[0] = s1[0];
            xp[1] = s2[1]; xp[2] = s2[2]; xp[3] = s2[3]; xp[4] = s2[4];
        }
        __syncthreads();

        // ---- layer 0 gates: pre0 + W_hh0 @ h0 ----
        ull acc[4][8];
#pragma unroll
        for (int p = 0; p < 8; p++) {
            const float* xa = xs + (sbase + 2 * p) * 5;
            const float* xb = xa + 5;
#pragma unroll
            for (int g = 0; g < 4; g++) {
                float lo = v2r[g], hi = v2r[g];
                lo = fmaf(xa[0], v1r[g], lo);
                hi = fmaf(xb[0], v1r[g], hi);
#pragma unroll
                for (int k = 0; k < 4; k++) {
                    lo = fmaf(xa[1 + k], wcr[g][k], lo);
                    hi = fmaf(xb[1 + k], wcr[g][k], hi);
                }
                acc[g][p] = pk2(lo, hi);
            }
        }
        mv64(acc, Wt0, h0T + sbase, u);
        __syncthreads();   // everyone done reading old h0

        // ---- layer 0 cell update ----
        {
            const int hbase = u * HP + sbase;
#pragma unroll
            for (int p = 0; p < 8; p++) {
                float i0, i1, f0, f1, g0, g1, o0, o1;
                upk2(acc[0][p], i0, i1);
                upk2(acc[1][p], f0, f1);
                upk2(acc[2][p], g0, g1);
                upk2(acc[3][p], o0, o1);
                float c = c0v[2 * p];
                c = sigm_(f0) * c + sigm_(i0) * tanh_(g0);
                c0v[2 * p] = c;
                h0T[hbase + 2 * p] = sigm_(o0) * tanh_(c);
                c = c0v[2 * p + 1];
                c = sigm_(f1) * c + sigm_(i1) * tanh_(g1);
                c0v[2 * p + 1] = c;
                h0T[hbase + 2 * p + 1] = sigm_(o1) * tanh_(c);
            }
        }
        __syncthreads();   // new h0 visible

        // ---- layer 1 gates: b1 + W_ih1 @ h0_new + W_hh1 @ h1_old ----
#pragma unroll
        for (int p = 0; p < 8; p++) {
#pragma unroll
            for (int g = 0; g < 4; g++) acc[g][p] = pk2(b1r[g], b1r[g]);
        }
        mv64(acc, Wt1, h0T + sbase, u);
        mv64(acc, Wt1 + 64 * 256, h1T + sbase, u);
        __syncthreads();   // everyone done reading old h1

        // ---- layer 1 cell update ----
        {
            const int hbase = u * HP + sbase;
#pragma unroll
            for (int p = 0; p < 8; p++) {
                float i0, i1, f0, f1, g0, g1, o0, o1;
                upk2(acc[0][p], i0, i1);
                upk2(acc[1][p], f0, f1);
                upk2(acc[2][p], g0, g1);
                upk2(acc[3][p], o0, o1);
                float c = c1v[2 * p];
                c = sigm_(f0) * c + sigm_(i0) * tanh_(g0);
                c1v[2 * p] = c;
                h1T[hbase + 2 * p] = sigm_(o0) * tanh_(c);
                c = c1v[2 * p + 1];
                c = sigm_(f1) * c + sigm_(i1) * tanh_(g1);
                c1v[2 * p + 1] = c;
                h1T[hbase + 2 * p + 1] = sigm_(o1) * tanh_(c);
            }
        }
        __syncthreads();   // new h1 visible

        // ---- head (only the last 48 steps produce output) ----
        if (t >= 335 && tid < SEQ) {
            float p0 = hb[0], p1 = hb[1];
#pragma unroll 8
            for (int j = 0; j < 64; j++) {
                float v = fmaxf(h1T[j * HP + tid], 0.f);
                p0 = fmaf(v, hw[j], p0);
                p1 = fmaf(v, hw[64 + j], p1);
            }
            float sp = (p1 > 15.f) ? p1 : log1pf(__expf(p1));
            int gs = gbase + tid;
            int b = gs >> 9, n = gs & 511;
            ((float2*)out)[((size_t)b * 48 + (t - 335)) * 512 + n] =
                make_float2(p0, sp);
        }
        // next iteration's first rewrite of h1T is 4 barriers away -> safe
    }
}

extern "C" void kernel_launch(void* const* d_in, const int* in_sizes, int n_in,
                              void* d_out, int out_size) {
    (void)in_sizes; (void)n_in; (void)out_size;
    const float* hist   = (const float*)d_in[0];
    const float* fut    = (const float*)d_in[1];
    const float* emb_W  = (const float*)d_in[2];
    const float* emb_b  = (const float*)d_in[3];
    const float* W_ih0  = (const float*)d_in[4];
    const float* W_hh0  = (const float*)d_in[5];
    const float* b_ih0  = (const float*)d_in[6];
    const float* b_hh0  = (const float*)d_in[7];
    const float* W_ih1  = (const float*)d_in[8];
    const float* W_hh1  = (const float*)d_in[9];
    const float* b_ih1  = (const float*)d_in[10];
    const float* b_hh1  = (const float*)d_in[11];
    const float* head_W = (const float*)d_in[12];
    const float* head_b = (const float*)d_in[13];
    float* out = (float*)d_out;

    cudaFuncSetAttribute(deepar_kernel,
                         cudaFuncAttributeMaxDynamicSharedMemorySize, SM_BYTES);

    deepar_kernel<<<NCTA, TPB, SM_BYTES>>>(
        hist, fut, emb_W, emb_b,
        W_ih0, W_hh0, b_ih0, b_hh0,
        W_ih1, W_hh1, b_ih1, b_hh1,
        head_W, head_b, out);
}